// round 13
// baseline (speedup 1.0000x reference)
#include <cuda_runtime.h>
#include <cuda_bf16.h>
#include <math.h>
#include <stdint.h>

// ---------------- problem constants ----------------
#define BB   4
#define NN   1024
#define KNB  32
#define CS   384
#define CZ   128
#define CH   16
#define HH   12
#define PQn  4
#define PVn  8
#define NODES (BB*NN)        // 4096
#define PROJ  1152           // q(192)+k(192)+v(192)+qpts(144)+kvpts(432)
#define EDGES (NODES*KNB)    // 131072
#define EOC   44             // b_bias(12) + pair(32)
#define EOCP  48             // padded W cols (float4-aligned groups of 12)
#define CVC   960            // o(192)+o_pt(288)+dists(96)+o_pair(384)
#define COUT  384
#define ZST   132            // z smem row stride (float4-aligned)

// ---------------- scratch (device globals; no allocation) ----------------
__device__ __nv_bfloat16 g_wcat_h[CS*PROJ];
__device__ __nv_bfloat16 g_wcat_l[CS*PROJ];
__device__ __nv_bfloat16 g_sln_h [NODES*CS];
__device__ __nv_bfloat16 g_sln_l [NODES*CS];
__device__ __nv_bfloat16 g_wout_h[CVC*COUT];
__device__ __nv_bfloat16 g_wout_l[CVC*COUT];
__device__ __nv_bfloat16 g_cvec_h[NODES*CVC];
__device__ __nv_bfloat16 g_cvec_l[NODES*CVC];
__device__ float g_proj[NODES*PROJ];
__device__ float g_wz  [CZ*EOC];
__device__ float g_eo  [EDGES*EOC];
__device__ float g_attn[NODES*HH*KNB];

// ---------------- helpers ----------------
__device__ __forceinline__ uint32_t smem_u32(const void* p) {
    uint32_t a;
    asm("{ .reg .u64 t; cvta.to.shared.u64 t, %1; cvt.u32.u64 %0, t; }"
        : "=r"(a) : "l"(p));
    return a;
}
__device__ __forceinline__ void cvt_hilo(float x, __nv_bfloat16& h, __nv_bfloat16& l) {
    h = __float2bfloat16(x);
    l = __float2bfloat16(x - __bfloat162float(h));
}
__device__ __forceinline__ void ldsm4(uint32_t& r0, uint32_t& r1, uint32_t& r2,
                                      uint32_t& r3, uint32_t addr) {
    asm volatile("ldmatrix.sync.aligned.m8n8.x4.shared.b16 {%0,%1,%2,%3}, [%4];"
                 : "=r"(r0), "=r"(r1), "=r"(r2), "=r"(r3) : "r"(addr));
}
__device__ __forceinline__ void ldsm4t(uint32_t& r0, uint32_t& r1, uint32_t& r2,
                                       uint32_t& r3, uint32_t addr) {
    asm volatile("ldmatrix.sync.aligned.m8n8.x4.trans.shared.b16 {%0,%1,%2,%3}, [%4];"
                 : "=r"(r0), "=r"(r1), "=r"(r2), "=r"(r3) : "r"(addr));
}
__device__ __forceinline__ void mma16816(float* c, const uint32_t* a, const uint32_t* b) {
    asm volatile(
        "mma.sync.aligned.m16n8k16.row.col.f32.bf16.bf16.f32 "
        "{%0,%1,%2,%3}, {%4,%5,%6,%7}, {%8,%9}, {%0,%1,%2,%3};"
        : "+f"(c[0]), "+f"(c[1]), "+f"(c[2]), "+f"(c[3])
        : "r"(a[0]), "r"(a[1]), "r"(a[2]), "r"(a[3]), "r"(b[0]), "r"(b[1]));
}

// ================= merged weight packing (fp32 -> bf16 hi/lo) ==============
#define NW1 (CS*PROJ)
#define NW2 (CVC*COUT)
#define NW3 (CZ*EOC)
__global__ void pack_all(const float* __restrict__ wq, const float* __restrict__ wk,
                         const float* __restrict__ wv, const float* __restrict__ wqp,
                         const float* __restrict__ wkv, const float* __restrict__ wo,
                         const float* __restrict__ wb, const float* __restrict__ wdz) {
    int idx = blockIdx.x * 256 + threadIdx.x;
    if (idx < NW1) {
        int i = idx / PROJ, j = idx % PROJ;
        float v;
        if      (j < 192) v = wq [i*192 + j];
        else if (j < 384) v = wk [i*192 + j - 192];
        else if (j < 576) v = wv [i*192 + j - 384];
        else if (j < 720) v = wqp[i*144 + j - 576];
        else              v = wkv[i*432 + j - 720];
        __nv_bfloat16 h, l;
        cvt_hilo(v, h, l);
        g_wcat_h[idx] = h;
        g_wcat_l[idx] = l;
    } else if (idx < NW1 + NW2) {
        int j = idx - NW1;
        __nv_bfloat16 h, l;
        cvt_hilo(wo[j], h, l);
        g_wout_h[j] = h;
        g_wout_l[j] = l;
    } else if (idx < NW1 + NW2 + NW3) {
        int t = idx - NW1 - NW2;
        int i = t / EOC, j = t % EOC;
        g_wz[t] = (j < 12) ? wb[i*12 + j] : wdz[i*32 + j - 12];
    }
}

// ---------------- s layernorm -> bf16 hi/lo (one block per node) ----------
__global__ __launch_bounds__(128) void k_ln_s(const float* __restrict__ s,
                                              const float* __restrict__ gam,
                                              const float* __restrict__ bet) {
    int node = blockIdx.x;
    int tid  = threadIdx.x;
    const float* x = s + (size_t)node * CS;
    float v0 = x[tid], v1 = x[tid + 128], v2 = x[tid + 256];
    float sum = v0 + v1 + v2;
    float ssq = v0*v0 + v1*v1 + v2*v2;
    #pragma unroll
    for (int o = 16; o; o >>= 1) {
        sum += __shfl_xor_sync(0xffffffffu, sum, o);
        ssq += __shfl_xor_sync(0xffffffffu, ssq, o);
    }
    __shared__ float sa[4], sb[4];
    int w = tid >> 5, l = tid & 31;
    if (l == 0) { sa[w] = sum; sb[w] = ssq; }
    __syncthreads();
    sum = sa[0] + sa[1] + sa[2] + sa[3];
    ssq = sb[0] + sb[1] + sb[2] + sb[3];
    float mean = sum * (1.0f / CS);
    float var  = ssq * (1.0f / CS) - mean * mean;
    float rstd = rsqrtf(var + 1e-5f);
    size_t base = (size_t)node * CS;
    #pragma unroll
    for (int i = 0; i < 3; i++) {
        float v = (i == 0) ? v0 : (i == 1) ? v1 : v2;
        int c = tid + i * 128;
        float y = (v - mean) * rstd * gam[c] + bet[c];
        __nv_bfloat16 h, lo;
        cvt_hilo(y, h, lo);
        g_sln_h[base + c] = h;
        g_sln_l[base + c] = lo;
    }
}

// ================= pure-bf16 tensor-core GEMM (3-term hi/lo) ===============
#define AST 40
#define BST 136

template<int BM>
__global__ __launch_bounds__(256, 2) void tgemm(const __nv_bfloat16* __restrict__ A_h,
                                                const __nv_bfloat16* __restrict__ A_l,
                                                const __nv_bfloat16* __restrict__ B_h,
                                                const __nv_bfloat16* __restrict__ B_l,
                                                float* __restrict__ C,
                                                int Kd, int Nd, int nk) {
    constexpr int MT = BM / 32;
    constexpr int AL = BM / 64;
    __shared__ __nv_bfloat16 Ah[BM * AST];
    __shared__ __nv_bfloat16 Al[BM * AST];
    __shared__ __nv_bfloat16 Bh[32 * BST];
    __shared__ __nv_bfloat16 Bl[32 * BST];

    int tid = threadIdx.x, wid = tid >> 5, lane = tid & 31;
    int m0 = blockIdx.x * BM, n0 = blockIdx.y * 128;
    int wm = (wid >> 2) * (BM / 2);
    int wn = (wid & 3) * 32;

    float acc[MT][4][4];
    #pragma unroll
    for (int i = 0; i < MT; i++)
        #pragma unroll
        for (int j = 0; j < 4; j++)
            #pragma unroll
            for (int r = 0; r < 4; r++) acc[i][j][r] = 0.f;

    uint32_t ah_base = smem_u32(Ah), al_base = smem_u32(Al);
    uint32_t bh_base = smem_u32(Bh), bl_base = smem_u32(Bl);

    int a_row = wm + (lane & 15);
    int a_col = (lane >> 4) << 3;
    int b_row = (lane & 7) + ((lane >> 3) & 1) * 8;
    int b_col = wn + ((lane >> 4) << 3);

    uint4 arh[AL], arl[AL], brh[2], brl[2];

    auto loadA = [&](int c) {
        int k0 = c * 32;
        #pragma unroll
        for (int t = 0; t < AL; t++) {
            int f = tid + t * 256;
            int row = f >> 2, col = (f & 3) * 8;
            size_t off = (size_t)(m0 + row) * Kd + k0 + col;
            arh[t] = *(const uint4*)(A_h + off);
            arl[t] = *(const uint4*)(A_l + off);
        }
    };
    auto loadB = [&](int c) {
        int k0 = c * 32;
        #pragma unroll
        for (int t = 0; t < 2; t++) {
            int f = tid + t * 256;
            int kr = f >> 4, nn = (f & 15) * 8;
            size_t off = (size_t)(k0 + kr) * Nd + n0 + nn;
            brh[t] = *(const uint4*)(B_h + off);
            brl[t] = *(const uint4*)(B_l + off);
        }
    };
    auto storeAB = [&]() {
        #pragma unroll
        for (int t = 0; t < AL; t++) {
            int f = tid + t * 256;
            int row = f >> 2, col = (f & 3) * 8;
            *(uint4*)&Ah[row*AST + col] = arh[t];
            *(uint4*)&Al[row*AST + col] = arl[t];
        }
        #pragma unroll
        for (int t = 0; t < 2; t++) {
            int f = tid + t * 256;
            int kr = f >> 4, nn = (f & 15) * 8;
            *(uint4*)&Bh[kr*BST + nn] = brh[t];
            *(uint4*)&Bl[kr*BST + nn] = brl[t];
        }
    };

    loadA(0); loadB(0);

    for (int c = 0; c < nk; c++) {
        storeAB();
        __syncthreads();
        if (c + 1 < nk) { loadA(c + 1); loadB(c + 1); }

        #pragma unroll
        for (int pass = 0; pass < 3; pass++) {
            uint32_t abase = (pass == 1) ? al_base : ah_base;
            uint32_t bbase = (pass == 2) ? bl_base : bh_base;
            #pragma unroll
            for (int ks = 0; ks < 32; ks += 16) {
                uint32_t af[MT][4];
                #pragma unroll
                for (int mt = 0; mt < MT; mt++) {
                    uint32_t addr = abase +
                        (uint32_t)(((a_row + mt*16) * AST + ks + a_col) * 2);
                    ldsm4(af[mt][0], af[mt][1], af[mt][2], af[mt][3], addr);
                }
                uint32_t bfr[4][2];
                #pragma unroll
                for (int nt16 = 0; nt16 < 2; nt16++) {
                    uint32_t addr = bbase +
                        (uint32_t)(((ks + b_row) * BST + b_col + nt16*16) * 2);
                    ldsm4t(bfr[nt16*2][0], bfr[nt16*2][1],
                           bfr[nt16*2+1][0], bfr[nt16*2+1][1], addr);
                }
                #pragma unroll
                for (int mt = 0; mt < MT; mt++)
                    #pragma unroll
                    for (int nt = 0; nt < 4; nt++)
                        mma16816(acc[mt][nt], af[mt], bfr[nt]);
            }
        }
        __syncthreads();
    }

    int er = lane >> 2;
    int ec = (lane & 3) * 2;
    #pragma unroll
    for (int mt = 0; mt < MT; mt++) {
        #pragma unroll
        for (int nt = 0; nt < 4; nt++) {
            int row = m0 + wm + mt*16 + er;
            int col = n0 + wn + nt*8 + ec;
            *(float2*)(C + (size_t)row * Nd + col) =
                make_float2(acc[mt][nt][0], acc[mt][nt][1]);
            *(float2*)(C + (size_t)(row + 8) * Nd + col) =
                make_float2(acc[mt][nt][2], acc[mt][nt][3]);
        }
    }
}

// ---------------- z GEMM: stats + LN fused, vectorized inner loop ----------
extern __shared__ float dynsm[];
__global__ __launch_bounds__(256) void k_zgemm(const float* __restrict__ z,
                                               const float* __restrict__ zsc,
                                               const float* __restrict__ zbi) {
    float* As      = dynsm;                  // [128][ZST]
    float* Ws      = dynsm + 128 * ZST;      // [128][EOCP=48]
    float* mean_sh = Ws + 128 * EOCP;        // [128]
    float* rstd_sh = mean_sh + 128;          // [128]
    int tid = threadIdx.x;
    int r0  = blockIdx.x * 128;

    for (int i = tid; i < CZ * EOCP; i += 256) {
        int row = i / EOCP, col = i % EOCP;
        Ws[i] = (col < EOC) ? g_wz[row * EOC + col] : 0.f;
    }
    #pragma unroll
    for (int t = 0; t < 16; t++) {
        int flat = (tid + t * 256) * 4;
        int row  = flat >> 7;
        int col  = flat & 127;
        *(float4*)&As[row*ZST + col] =
            *(const float4*)(z + (size_t)(r0 + row) * CZ + col);
    }
    __syncthreads();
    {
        int w = tid >> 5, lane = tid & 31;
        for (int rr = 0; rr < 16; rr++) {
            int row = w * 16 + rr;
            float s1 = 0.f, s2 = 0.f;
            #pragma unroll
            for (int c = 0; c < 4; c++) {
                float v = As[row*ZST + lane + c * 32];
                s1 += v; s2 += v * v;
            }
            #pragma unroll
            for (int o = 16; o; o >>= 1) {
                s1 += __shfl_xor_sync(0xffffffffu, s1, o);
                s2 += __shfl_xor_sync(0xffffffffu, s2, o);
            }
            if (lane == 0) {
                float mean = s1 * (1.0f / CZ);
                float var  = s2 * (1.0f / CZ) - mean * mean;
                mean_sh[row] = mean;
                rstd_sh[row] = rsqrtf(var + 1e-5f);
            }
        }
    }
    __syncthreads();
    #pragma unroll
    for (int t = 0; t < 16; t++) {
        int flat = (tid + t * 256) * 4;
        int row  = flat >> 7;
        int col  = flat & 127;
        float mean = mean_sh[row], rstd = rstd_sh[row];
        float4 v = *(float4*)&As[row*ZST + col];
        v.x = (v.x - mean) * rstd * __ldg(zsc + col + 0) + __ldg(zbi + col + 0);
        v.y = (v.y - mean) * rstd * __ldg(zsc + col + 1) + __ldg(zbi + col + 1);
        v.z = (v.z - mean) * rstd * __ldg(zsc + col + 2) + __ldg(zbi + col + 2);
        v.w = (v.w - mean) * rstd * __ldg(zsc + col + 3) + __ldg(zbi + col + 3);
        *(float4*)&As[row*ZST + col] = v;
    }
    __syncthreads();

    // compute: thread -> rows {rA, rA+64}, cols c0..c0+11; k stepped by 4
    int rA = tid >> 2;
    int rB = rA + 64;
    int c0 = (tid & 3) * 12;
    float acc0[12], acc1[12];
    #pragma unroll
    for (int j = 0; j < 12; j++) { acc0[j] = 0.f; acc1[j] = 0.f; }
    #pragma unroll 4
    for (int kk = 0; kk < CZ; kk += 4) {
        float4 a0 = *(float4*)&As[rA*ZST + kk];
        float4 a1 = *(float4*)&As[rB*ZST + kk];
        #pragma unroll
        for (int t = 0; t < 4; t++) {
            float av0 = (t == 0) ? a0.x : (t == 1) ? a0.y : (t == 2) ? a0.z : a0.w;
            float av1 = (t == 0) ? a1.x : (t == 1) ? a1.y : (t == 2) ? a1.z : a1.w;
            const float* wp = &Ws[(kk + t) * EOCP + c0];
            float4 w0 = *(const float4*)(wp);
            float4 w1 = *(const float4*)(wp + 4);
            float4 w2 = *(const float4*)(wp + 8);
            acc0[0] += av0 * w0.x; acc1[0] += av1 * w0.x;
            acc0[1] += av0 * w0.y; acc1[1] += av1 * w0.y;
            acc0[2] += av0 * w0.z; acc1[2] += av1 * w0.z;
            acc0[3] += av0 * w0.w; acc1[3] += av1 * w0.w;
            acc0[4] += av0 * w1.x; acc1[4] += av1 * w1.x;
            acc0[5] += av0 * w1.y; acc1[5] += av1 * w1.y;
            acc0[6] += av0 * w1.z; acc1[6] += av1 * w1.z;
            acc0[7] += av0 * w1.w; acc1[7] += av1 * w1.w;
            acc0[8] += av0 * w2.x; acc1[8] += av1 * w2.x;
            acc0[9] += av0 * w2.y; acc1[9] += av1 * w2.y;
            acc0[10] += av0 * w2.z; acc1[10] += av1 * w2.z;
            acc0[11] += av0 * w2.w; acc1[11] += av1 * w2.w;
        }
    }
    #pragma unroll
    for (int j = 0; j < 12; j++) {
        int col = c0 + j;
        if (col < EOC) {
            g_eo[(size_t)(r0 + rA) * EOC + col] = acc0[j];
            g_eo[(size_t)(r0 + rB) * EOC + col] = acc1[j];
        }
    }
}

// ---------------- attention logits: one block (256 thr) per node -----------
#define KST 337   // smem row stride (floats): 192 k + 144 kpts

__global__ __launch_bounds__(256) void k_attn_logits(const int*   __restrict__ edge_index,
                                                     const float* __restrict__ s_mask,
                                                     const float* __restrict__ head_w) {
    float* kv_sh = dynsm;              // [KNB][KST]
    int node = blockIdx.x;
    int tid  = threadIdx.x;
    int b    = node >> 10;

    __shared__ int   nbroff_sh[KNB];
    __shared__ float msk_sh[KNB];
    __shared__ float q_sh[HH * CH];
    __shared__ float qp_sh[HH * PQn * 3];
    __shared__ float hw_sh[HH];
    __shared__ float b_sh[HH][KNB];

    if (tid < KNB) {
        int idx = edge_index[(size_t)node * KNB + tid];
        nbroff_sh[tid] = (b * NN + idx) * PROJ;
        msk_sh[tid]    = s_mask[node] * s_mask[b * NN + idx];
    }
    if (tid < HH)
        hw_sh[tid] = log1pf(__expf(head_w[tid])) * 0.13608276348795434f;
    __syncthreads();

    for (int idx = tid; idx < KNB * 192; idx += 256) {
        int k = idx / 192, c = idx - k * 192;
        kv_sh[k * KST + c] = g_proj[nbroff_sh[k] + 192 + c];
    }
    for (int idx = tid; idx < KNB * 144; idx += 256) {
        int k = idx / 144, j = idx - k * 144;
        int h = j / 12, r = j - h * 12;
        kv_sh[k * KST + 192 + j] = g_proj[nbroff_sh[k] + 720 + h * 36 + r];
    }
    for (int idx = tid; idx < KNB * HH; idx += 256) {
        int k = idx / HH, h = idx - k * HH;
        b_sh[h][k] = g_eo[(size_t)(node * KNB + k) * EOC + h];
    }
    for (int i = tid; i < HH * CH; i += 256)
        q_sh[i] = g_proj[(size_t)node * PROJ + i];
    for (int i = tid; i < HH * PQn * 3; i += 256)
        qp_sh[i] = g_proj[(size_t)node * PROJ + 576 + i];
    __syncthreads();

    int lane = tid & 31, warp = tid >> 5;
    float mk = msk_sh[lane];
    const float* kr = kv_sh + lane * KST;
    float* ga = g_attn + (size_t)node * HH * KNB;

    #pragma unroll
    for (int rep = 0; rep < 2; rep++) {
        if (rep == 1 && warp >= 4) break;
        int h = (rep == 0) ? warp : 8 + warp;
        float dot = 0.f;
        #pragma unroll
        for (int c = 0; c < 16; c++)
            dot += q_sh[h * CH + c] * kr[h * CH + c];
        float sq = 0.f;
        #pragma unroll
        for (int j = 0; j < 12; j++) {
            float d = qp_sh[h * 12 + j] - kr[192 + h * 12 + j];
            sq += d * d;
        }
        float logit = dot * 0.14433756729740643f
                    + b_sh[h][lane] * 0.5773502691896258f
                    - 0.5f * hw_sh[h] * sq
                    + 100000.0f * (mk - 1.0f);
        float mx = logit;
        #pragma unroll
        for (int o = 16; o; o >>= 1) mx = fmaxf(mx, __shfl_xor_sync(0xffffffffu, mx, o));
        float e = __expf(logit - mx);
        float sm = e;
        #pragma unroll
        for (int o = 16; o; o >>= 1) sm += __shfl_xor_sync(0xffffffffu, sm, o);
        ga[h * KNB + lane] = e / sm;
    }
}

// ---------------- attention output: one block (256 thr) per node ----------
__global__ __launch_bounds__(256) void k_attn_out(const int* __restrict__ edge_index) {
    int node = blockIdx.x;
    int tid  = threadIdx.x;
    int b    = node >> 10;

    __shared__ int   nbroff_sh[KNB];
    __shared__ float a_sh[HH][KNB];
    __shared__ float opt_sh[HH * PVn * 3];

    if (tid < KNB) {
        int idx = edge_index[(size_t)node * KNB + tid];
        nbroff_sh[tid] = (b * NN + idx) * PROJ;
    }
    {
        const float* ga = g_attn + (size_t)node * HH * KNB;
        for (int i = tid; i < HH * KNB; i += 256)
            a_sh[i >> 5][i & 31] = ga[i];
    }
    __syncthreads();

    size_t cvb = (size_t)node * CVC;
    for (int oi = tid; oi < CVC; oi += 256) {
        float acc = 0.f;
        bool have = false;
        if (oi < 192) {
            int h = oi >> 4;
            int off = 384 + oi;
            #pragma unroll 8
            for (int k = 0; k < KNB; k++)
                acc += a_sh[h][k] * g_proj[nbroff_sh[k] + off];
            have = true;
        } else if (oi < 480) {
            int j = oi - 192;
            int h = j / 24, r = j % 24;
            int off = 720 + h * 36 + 12 + r;
            #pragma unroll 8
            for (int k = 0; k < KNB; k++)
                acc += a_sh[h][k] * g_proj[nbroff_sh[k] + off];
            opt_sh[j] = acc;
            have = true;
        } else if (oi >= 576) {
            int j = oi - 576;
            int h = j >> 5, c = j & 31;
            const float* eb = g_eo + (size_t)(node * KNB) * EOC + 12 + c;
            #pragma unroll 8
            for (int k = 0; k < KNB; k++)
                acc += a_sh[h][k] * eb[(size_t)k * EOC];
            have = true;
        }
        if (have) {
            __nv_bfloat16 h16, l16;
            cvt_hilo(acc, h16, l16);
            g_cvec_h[cvb + oi] = h16;
            g_cvec_l[cvb + oi] = l16;
        }
    }
    __syncthreads();
    if (tid < HH * PVn) {
        float x = opt_sh[tid*3], y = opt_sh[tid*3+1], zz = opt_sh[tid*3+2];
        float d = sqrtf(x*x + y*y + zz*zz + 1e-8f);
        __nv_bfloat16 h16, l16;
        cvt_hilo(d, h16, l16);
        g_cvec_h[cvb + 480 + tid] = h16;
        g_cvec_l[cvb + 480 + tid] = l16;
    }
}

// ---------------- launch ----------------
extern "C" void kernel_launch(void* const* d_in, const int* in_sizes, int n_in,
                              void* d_out, int out_size) {
    const float* s           = (const float*)d_in[0];
    const float* z           = (const float*)d_in[1];
    const int*   edge_index  = (const int*)  d_in[2];
    // d_in[3] rot, d_in[4] trans: cancel algebraically -> unused
    const float* s_mask      = (const float*)d_in[5];
    const float* ln_s_scale  = (const float*)d_in[6];
    const float* ln_s_bias   = (const float*)d_in[7];
    const float* ln_z_scale  = (const float*)d_in[8];
    const float* ln_z_bias   = (const float*)d_in[9];
    const float* w_q         = (const float*)d_in[10];
    const float* w_k         = (const float*)d_in[11];
    const float* w_v         = (const float*)d_in[12];
    const float* w_q_pts     = (const float*)d_in[13];
    const float* w_kv_pts    = (const float*)d_in[14];
    const float* w_b         = (const float*)d_in[15];
    const float* w_down_z    = (const float*)d_in[16];
    const float* head_weights= (const float*)d_in[17];
    const float* w_out       = (const float*)d_in[18];
    float* out = (float*)d_out;

    const int zsmem = (128 * ZST + 128 * EOCP + 256) * sizeof(float);
    cudaFuncSetAttribute(k_zgemm, cudaFuncAttributeMaxDynamicSharedMemorySize, zsmem);

    void *p_wcat_h, *p_wcat_l, *p_sln_h, *p_sln_l;
    void *p_wout_h, *p_wout_l, *p_cvec_h, *p_cvec_l, *p_proj;
    cudaGetSymbolAddress(&p_wcat_h, g_wcat_h);
    cudaGetSymbolAddress(&p_wcat_l, g_wcat_l);
    cudaGetSymbolAddress(&p_sln_h,  g_sln_h);
    cudaGetSymbolAddress(&p_sln_l,  g_sln_l);
    cudaGetSymbolAddress(&p_wout_h, g_wout_h);
    cudaGetSymbolAddress(&p_wout_l, g_wout_l);
    cudaGetSymbolAddress(&p_cvec_h, g_cvec_h);
    cudaGetSymbolAddress(&p_cvec_l, g_cvec_l);
    cudaGetSymbolAddress(&p_proj,   g_proj);

    pack_all<<<(NW1 + NW2 + NW3 + 255) / 256, 256>>>(
        w_q, w_k, w_v, w_q_pts, w_kv_pts, w_out, w_b, w_down_z);
    k_ln_s<<<NODES, 128>>>(s, ln_s_scale, ln_s_bias);

    // GEMM1: LN(s) @ wcat -> proj   (4096x384)@(384x1152), pure bf16
    tgemm<128><<<dim3(NODES/128, PROJ/128), 256>>>(
        (const __nv_bfloat16*)p_sln_h, (const __nv_bfloat16*)p_sln_l,
        (const __nv_bfloat16*)p_wcat_h, (const __nv_bfloat16*)p_wcat_l,
        (float*)p_proj, CS, PROJ, CS/32);

    // z path (stats + LN + GEMM in one kernel, single z read)
    k_zgemm<<<EDGES / 128, 256, zsmem>>>(z, ln_z_scale, ln_z_bias);

    // attention: logits (smem-heavy, short) then output (occupancy-heavy)
    k_attn_logits<<<NODES, 256, KNB * KST * sizeof(float)>>>(
        edge_index, s_mask, head_weights);
    k_attn_out<<<NODES, 256>>>(edge_index);

    // GEMM2: cvec @ w_out -> out    (4096x960)@(960x384), pure bf16, 64-tiles
    tgemm<64><<<dim3(NODES/64, COUT/128), 256>>>(
        (const __nv_bfloat16*)p_cvec_h, (const __nv_bfloat16*)p_cvec_l,
        (const __nv_bfloat16*)p_wout_h, (const __nv_bfloat16*)p_wout_l,
        out, CVC, COUT, CVC/32);
}

// round 15
// speedup vs baseline: 1.1078x; 1.1078x over previous
#include <cuda_runtime.h>
#include <cuda_bf16.h>
#include <math.h>
#include <stdint.h>

// ---------------- problem constants ----------------
#define BB   4
#define NN   1024
#define KNB  32
#define CS   384
#define CZ   128
#define CH   16
#define HH   12
#define PQn  4
#define PVn  8
#define NODES (BB*NN)        // 4096
#define PROJ  1152           // q(192)+k(192)+v(192)+qpts(144)+kvpts(432)
#define EDGES (NODES*KNB)    // 131072
#define EOC   44             // b_bias(12) + pair(32)
#define EOCP  48             // padded W cols
#define CVC   960            // o(192)+o_pt(288)+dists(96)+o_pair(384)
#define COUT  384
#define ZST   132            // z smem row stride (float4-aligned)

// ---------------- scratch (device globals; no allocation) ----------------
__device__ __nv_bfloat16 g_wcat_h[CS*PROJ];
__device__ __nv_bfloat16 g_wcat_l[CS*PROJ];
__device__ __nv_bfloat16 g_sln_h [NODES*CS];
__device__ __nv_bfloat16 g_sln_l [NODES*CS];
__device__ __nv_bfloat16 g_wout_h[CVC*COUT];
__device__ __nv_bfloat16 g_wout_l[CVC*COUT];
__device__ __nv_bfloat16 g_cvec_h[NODES*CVC];
__device__ __nv_bfloat16 g_cvec_l[NODES*CVC];
__device__ float g_proj[NODES*PROJ];
__device__ float g_wz  [CZ*EOC];
__device__ float g_eo  [EDGES*EOC];
__device__ float g_attn[NODES*HH*KNB];

// ---------------- helpers ----------------
__device__ __forceinline__ uint32_t smem_u32(const void* p) {
    uint32_t a;
    asm("{ .reg .u64 t; cvta.to.shared.u64 t, %1; cvt.u32.u64 %0, t; }"
        : "=r"(a) : "l"(p));
    return a;
}
__device__ __forceinline__ void cvt_hilo(float x, __nv_bfloat16& h, __nv_bfloat16& l) {
    h = __float2bfloat16(x);
    l = __float2bfloat16(x - __bfloat162float(h));
}
__device__ __forceinline__ void ldsm4(uint32_t& r0, uint32_t& r1, uint32_t& r2,
                                      uint32_t& r3, uint32_t addr) {
    asm volatile("ldmatrix.sync.aligned.m8n8.x4.shared.b16 {%0,%1,%2,%3}, [%4];"
                 : "=r"(r0), "=r"(r1), "=r"(r2), "=r"(r3) : "r"(addr));
}
__device__ __forceinline__ void ldsm4t(uint32_t& r0, uint32_t& r1, uint32_t& r2,
                                       uint32_t& r3, uint32_t addr) {
    asm volatile("ldmatrix.sync.aligned.m8n8.x4.trans.shared.b16 {%0,%1,%2,%3}, [%4];"
                 : "=r"(r0), "=r"(r1), "=r"(r2), "=r"(r3) : "r"(addr));
}
__device__ __forceinline__ void mma16816(float* c, const uint32_t* a, const uint32_t* b) {
    asm volatile(
        "mma.sync.aligned.m16n8k16.row.col.f32.bf16.bf16.f32 "
        "{%0,%1,%2,%3}, {%4,%5,%6,%7}, {%8,%9}, {%0,%1,%2,%3};"
        : "+f"(c[0]), "+f"(c[1]), "+f"(c[2]), "+f"(c[3])
        : "r"(a[0]), "r"(a[1]), "r"(a[2]), "r"(a[3]), "r"(b[0]), "r"(b[1]));
}

// ================= merged weight packing (fp32 -> bf16 hi/lo) ==============
#define NW1 (CS*PROJ)
#define NW2 (CVC*COUT)
#define NW3 (CZ*EOC)
__global__ void pack_all(const float* __restrict__ wq, const float* __restrict__ wk,
                         const float* __restrict__ wv, const float* __restrict__ wqp,
                         const float* __restrict__ wkv, const float* __restrict__ wo,
                         const float* __restrict__ wb, const float* __restrict__ wdz) {
    int idx = blockIdx.x * 256 + threadIdx.x;
    if (idx < NW1) {
        int i = idx / PROJ, j = idx % PROJ;
        float v;
        if      (j < 192) v = wq [i*192 + j];
        else if (j < 384) v = wk [i*192 + j - 192];
        else if (j < 576) v = wv [i*192 + j - 384];
        else if (j < 720) v = wqp[i*144 + j - 576];
        else              v = wkv[i*432 + j - 720];
        __nv_bfloat16 h, l;
        cvt_hilo(v, h, l);
        g_wcat_h[idx] = h;
        g_wcat_l[idx] = l;
    } else if (idx < NW1 + NW2) {
        int j = idx - NW1;
        __nv_bfloat16 h, l;
        cvt_hilo(wo[j], h, l);
        g_wout_h[j] = h;
        g_wout_l[j] = l;
    } else if (idx < NW1 + NW2 + NW3) {
        int t = idx - NW1 - NW2;
        int i = t / EOC, j = t % EOC;
        g_wz[t] = (j < 12) ? wb[i*12 + j] : wdz[i*32 + j - 12];
    }
}

// ---------------- s layernorm -> bf16 hi/lo (one block per node) ----------
__global__ __launch_bounds__(128) void k_ln_s(const float* __restrict__ s,
                                              const float* __restrict__ gam,
                                              const float* __restrict__ bet) {
    int node = blockIdx.x;
    int tid  = threadIdx.x;
    const float* x = s + (size_t)node * CS;
    float v0 = x[tid], v1 = x[tid + 128], v2 = x[tid + 256];
    float sum = v0 + v1 + v2;
    float ssq = v0*v0 + v1*v1 + v2*v2;
    #pragma unroll
    for (int o = 16; o; o >>= 1) {
        sum += __shfl_xor_sync(0xffffffffu, sum, o);
        ssq += __shfl_xor_sync(0xffffffffu, ssq, o);
    }
    __shared__ float sa[4], sb[4];
    int w = tid >> 5, l = tid & 31;
    if (l == 0) { sa[w] = sum; sb[w] = ssq; }
    __syncthreads();
    sum = sa[0] + sa[1] + sa[2] + sa[3];
    ssq = sb[0] + sb[1] + sb[2] + sb[3];
    float mean = sum * (1.0f / CS);
    float var  = ssq * (1.0f / CS) - mean * mean;
    float rstd = rsqrtf(var + 1e-5f);
    size_t base = (size_t)node * CS;
    #pragma unroll
    for (int i = 0; i < 3; i++) {
        float v = (i == 0) ? v0 : (i == 1) ? v1 : v2;
        int c = tid + i * 128;
        float y = (v - mean) * rstd * gam[c] + bet[c];
        __nv_bfloat16 h, lo;
        cvt_hilo(y, h, lo);
        g_sln_h[base + c] = h;
        g_sln_l[base + c] = lo;
    }
}

// ================= pure-bf16 tensor-core GEMM (3-term hi/lo) ===============
#define AST 40
#define BST 136

template<int BM>
__global__ __launch_bounds__(256, 2) void tgemm(const __nv_bfloat16* __restrict__ A_h,
                                                const __nv_bfloat16* __restrict__ A_l,
                                                const __nv_bfloat16* __restrict__ B_h,
                                                const __nv_bfloat16* __restrict__ B_l,
                                                float* __restrict__ C,
                                                int Kd, int Nd, int nk) {
    constexpr int MT = BM / 32;
    constexpr int AL = BM / 64;
    __shared__ __nv_bfloat16 Ah[BM * AST];
    __shared__ __nv_bfloat16 Al[BM * AST];
    __shared__ __nv_bfloat16 Bh[32 * BST];
    __shared__ __nv_bfloat16 Bl[32 * BST];

    int tid = threadIdx.x, wid = tid >> 5, lane = tid & 31;
    int m0 = blockIdx.x * BM, n0 = blockIdx.y * 128;
    int wm = (wid >> 2) * (BM / 2);
    int wn = (wid & 3) * 32;

    float acc[MT][4][4];
    #pragma unroll
    for (int i = 0; i < MT; i++)
        #pragma unroll
        for (int j = 0; j < 4; j++)
            #pragma unroll
            for (int r = 0; r < 4; r++) acc[i][j][r] = 0.f;

    uint32_t ah_base = smem_u32(Ah), al_base = smem_u32(Al);
    uint32_t bh_base = smem_u32(Bh), bl_base = smem_u32(Bl);

    int a_row = wm + (lane & 15);
    int a_col = (lane >> 4) << 3;
    int b_row = (lane & 7) + ((lane >> 3) & 1) * 8;
    int b_col = wn + ((lane >> 4) << 3);

    uint4 arh[AL], arl[AL], brh[2], brl[2];

    auto loadA = [&](int c) {
        int k0 = c * 32;
        #pragma unroll
        for (int t = 0; t < AL; t++) {
            int f = tid + t * 256;
            int row = f >> 2, col = (f & 3) * 8;
            size_t off = (size_t)(m0 + row) * Kd + k0 + col;
            arh[t] = *(const uint4*)(A_h + off);
            arl[t] = *(const uint4*)(A_l + off);
        }
    };
    auto loadB = [&](int c) {
        int k0 = c * 32;
        #pragma unroll
        for (int t = 0; t < 2; t++) {
            int f = tid + t * 256;
            int kr = f >> 4, nn = (f & 15) * 8;
            size_t off = (size_t)(k0 + kr) * Nd + n0 + nn;
            brh[t] = *(const uint4*)(B_h + off);
            brl[t] = *(const uint4*)(B_l + off);
        }
    };
    auto storeAB = [&]() {
        #pragma unroll
        for (int t = 0; t < AL; t++) {
            int f = tid + t * 256;
            int row = f >> 2, col = (f & 3) * 8;
            *(uint4*)&Ah[row*AST + col] = arh[t];
            *(uint4*)&Al[row*AST + col] = arl[t];
        }
        #pragma unroll
        for (int t = 0; t < 2; t++) {
            int f = tid + t * 256;
            int kr = f >> 4, nn = (f & 15) * 8;
            *(uint4*)&Bh[kr*BST + nn] = brh[t];
            *(uint4*)&Bl[kr*BST + nn] = brl[t];
        }
    };

    loadA(0); loadB(0);

    for (int c = 0; c < nk; c++) {
        storeAB();
        __syncthreads();
        if (c + 1 < nk) { loadA(c + 1); loadB(c + 1); }

        #pragma unroll
        for (int pass = 0; pass < 3; pass++) {
            uint32_t abase = (pass == 1) ? al_base : ah_base;
            uint32_t bbase = (pass == 2) ? bl_base : bh_base;
            #pragma unroll
            for (int ks = 0; ks < 32; ks += 16) {
                uint32_t af[MT][4];
                #pragma unroll
                for (int mt = 0; mt < MT; mt++) {
                    uint32_t addr = abase +
                        (uint32_t)(((a_row + mt*16) * AST + ks + a_col) * 2);
                    ldsm4(af[mt][0], af[mt][1], af[mt][2], af[mt][3], addr);
                }
                uint32_t bfr[4][2];
                #pragma unroll
                for (int nt16 = 0; nt16 < 2; nt16++) {
                    uint32_t addr = bbase +
                        (uint32_t)(((ks + b_row) * BST + b_col + nt16*16) * 2);
                    ldsm4t(bfr[nt16*2][0], bfr[nt16*2][1],
                           bfr[nt16*2+1][0], bfr[nt16*2+1][1], addr);
                }
                #pragma unroll
                for (int mt = 0; mt < MT; mt++)
                    #pragma unroll
                    for (int nt = 0; nt < 4; nt++)
                        mma16816(acc[mt][nt], af[mt], bfr[nt]);
            }
        }
        __syncthreads();
    }

    int er = lane >> 2;
    int ec = (lane & 3) * 2;
    #pragma unroll
    for (int mt = 0; mt < MT; mt++) {
        #pragma unroll
        for (int nt = 0; nt < 4; nt++) {
            int row = m0 + wm + mt*16 + er;
            int col = n0 + wn + nt*8 + ec;
            *(float2*)(C + (size_t)row * Nd + col) =
                make_float2(acc[mt][nt][0], acc[mt][nt][1]);
            *(float2*)(C + (size_t)(row + 8) * Nd + col) =
                make_float2(acc[mt][nt][2], acc[mt][nt][3]);
        }
    }
}

// ---------------- z GEMM: stats + LN fused; TM=4 x TN=6 register blocking --
extern __shared__ float dynsm[];
__global__ __launch_bounds__(256) void k_zgemm(const float* __restrict__ z,
                                               const float* __restrict__ zsc,
                                               const float* __restrict__ zbi) {
    float* As      = dynsm;                  // [128][ZST]
    float* Ws      = dynsm + 128 * ZST;      // [128][EOCP=48]
    float* mean_sh = Ws + 128 * EOCP;        // [128]
    float* rstd_sh = mean_sh + 128;          // [128]
    int tid = threadIdx.x;
    int r0  = blockIdx.x * 128;

    for (int i = tid; i < CZ * EOCP; i += 256) {
        int row = i / EOCP, col = i % EOCP;
        Ws[i] = (col < EOC) ? g_wz[row * EOC + col] : 0.f;
    }
    #pragma unroll
    for (int t = 0; t < 16; t++) {
        int flat = (tid + t * 256) * 4;
        int row  = flat >> 7;
        int col  = flat & 127;
        *(float4*)&As[row*ZST + col] =
            *(const float4*)(z + (size_t)(r0 + row) * CZ + col);
    }
    __syncthreads();
    {
        int w = tid >> 5, lane = tid & 31;
        for (int rr = 0; rr < 16; rr++) {
            int row = w * 16 + rr;
            float s1 = 0.f, s2 = 0.f;
            #pragma unroll
            for (int c = 0; c < 4; c++) {
                float v = As[row*ZST + lane + c * 32];
                s1 += v; s2 += v * v;
            }
            #pragma unroll
            for (int o = 16; o; o >>= 1) {
                s1 += __shfl_xor_sync(0xffffffffu, s1, o);
                s2 += __shfl_xor_sync(0xffffffffu, s2, o);
            }
            if (lane == 0) {
                float mean = s1 * (1.0f / CZ);
                float var  = s2 * (1.0f / CZ) - mean * mean;
                mean_sh[row] = mean;
                rstd_sh[row] = rsqrtf(var + 1e-5f);
            }
        }
    }
    __syncthreads();
    #pragma unroll
    for (int t = 0; t < 16; t++) {
        int flat = (tid + t * 256) * 4;
        int row  = flat >> 7;
        int col  = flat & 127;
        float mean = mean_sh[row], rstd = rstd_sh[row];
        float4 v = *(float4*)&As[row*ZST + col];
        v.x = (v.x - mean) * rstd * __ldg(zsc + col + 0) + __ldg(zbi + col + 0);
        v.y = (v.y - mean) * rstd * __ldg(zsc + col + 1) + __ldg(zbi + col + 1);
        v.z = (v.z - mean) * rstd * __ldg(zsc + col + 2) + __ldg(zbi + col + 2);
        v.w = (v.w - mean) * rstd * __ldg(zsc + col + 3) + __ldg(zbi + col + 3);
        *(float4*)&As[row*ZST + col] = v;
    }
    __syncthreads();

    // compute: thread -> 4 rows (row0..row0+3) x 6 cols (c0..c0+5)
    // A: float4 along k per row (8-lane broadcast); W: scalar (4-lane bcast)
    int row0 = (tid >> 3) * 4;
    int c0   = (tid & 7) * 6;
    float acc[4][6];
    #pragma unroll
    for (int i = 0; i < 4; i++)
        #pragma unroll
        for (int j = 0; j < 6; j++) acc[i][j] = 0.f;

    #pragma unroll 2
    for (int kk = 0; kk < CZ; kk += 4) {
        float4 a[4];
        #pragma unroll
        for (int i = 0; i < 4; i++)
            a[i] = *(float4*)&As[(row0 + i)*ZST + kk];
        #pragma unroll
        for (int t = 0; t < 4; t++) {
            const float* wp = &Ws[(kk + t) * EOCP + c0];
            float w0 = wp[0], w1 = wp[1], w2 = wp[2];
            float w3 = wp[3], w4 = wp[4], w5 = wp[5];
            #pragma unroll
            for (int i = 0; i < 4; i++) {
                float av = (t == 0) ? a[i].x : (t == 1) ? a[i].y
                         : (t == 2) ? a[i].z : a[i].w;
                acc[i][0] += av * w0;
                acc[i][1] += av * w1;
                acc[i][2] += av * w2;
                acc[i][3] += av * w3;
                acc[i][4] += av * w4;
                acc[i][5] += av * w5;
            }
        }
    }
    #pragma unroll
    for (int i = 0; i < 4; i++) {
        #pragma unroll
        for (int j = 0; j < 6; j++) {
            int col = c0 + j;
            if (col < EOC)
                g_eo[(size_t)(r0 + row0 + i) * EOC + col] = acc[i][j];
        }
    }
}

// ---------------- attention logits: one block (256 thr) per node -----------
#define KST 337   // smem row stride (floats): 192 k + 144 kpts

__global__ __launch_bounds__(256) void k_attn_logits(const int*   __restrict__ edge_index,
                                                     const float* __restrict__ s_mask,
                                                     const float* __restrict__ head_w) {
    float* kv_sh = dynsm;              // [KNB][KST]
    int node = blockIdx.x;
    int tid  = threadIdx.x;
    int b    = node >> 10;

    __shared__ int   nbroff_sh[KNB];
    __shared__ float msk_sh[KNB];
    __shared__ float q_sh[HH * CH];
    __shared__ float qp_sh[HH * PQn * 3];
    __shared__ float hw_sh[HH];
    __shared__ float b_sh[HH][KNB];

    if (tid < KNB) {
        int idx = edge_index[(size_t)node * KNB + tid];
        nbroff_sh[tid] = (b * NN + idx) * PROJ;
        msk_sh[tid]    = s_mask[node] * s_mask[b * NN + idx];
    }
    if (tid < HH)
        hw_sh[tid] = log1pf(__expf(head_w[tid])) * 0.13608276348795434f;
    __syncthreads();

    for (int idx = tid; idx < KNB * 192; idx += 256) {
        int k = idx / 192, c = idx - k * 192;
        kv_sh[k * KST + c] = g_proj[nbroff_sh[k] + 192 + c];
    }
    for (int idx = tid; idx < KNB * 144; idx += 256) {
        int k = idx / 144, j = idx - k * 144;
        int h = j / 12, r = j - h * 12;
        kv_sh[k * KST + 192 + j] = g_proj[nbroff_sh[k] + 720 + h * 36 + r];
    }
    for (int idx = tid; idx < KNB * HH; idx += 256) {
        int k = idx / HH, h = idx - k * HH;
        b_sh[h][k] = g_eo[(size_t)(node * KNB + k) * EOC + h];
    }
    for (int i = tid; i < HH * CH; i += 256)
        q_sh[i] = g_proj[(size_t)node * PROJ + i];
    for (int i = tid; i < HH * PQn * 3; i += 256)
        qp_sh[i] = g_proj[(size_t)node * PROJ + 576 + i];
    __syncthreads();

    int lane = tid & 31, warp = tid >> 5;
    float mk = msk_sh[lane];
    const float* kr = kv_sh + lane * KST;
    float* ga = g_attn + (size_t)node * HH * KNB;

    #pragma unroll
    for (int rep = 0; rep < 2; rep++) {
        if (rep == 1 && warp >= 4) break;
        int h = (rep == 0) ? warp : 8 + warp;
        float dot = 0.f;
        #pragma unroll
        for (int c = 0; c < 16; c++)
            dot += q_sh[h * CH + c] * kr[h * CH + c];
        float sq = 0.f;
        #pragma unroll
        for (int j = 0; j < 12; j++) {
            float d = qp_sh[h * 12 + j] - kr[192 + h * 12 + j];
            sq += d * d;
        }
        float logit = dot * 0.14433756729740643f
                    + b_sh[h][lane] * 0.5773502691896258f
                    - 0.5f * hw_sh[h] * sq
                    + 100000.0f * (mk - 1.0f);
        float mx = logit;
        #pragma unroll
        for (int o = 16; o; o >>= 1) mx = fmaxf(mx, __shfl_xor_sync(0xffffffffu, mx, o));
        float e = __expf(logit - mx);
        float sm = e;
        #pragma unroll
        for (int o = 16; o; o >>= 1) sm += __shfl_xor_sync(0xffffffffu, sm, o);
        ga[h * KNB + lane] = e / sm;
    }
}

// ---------------- attention output: one block (256 thr) per node ----------
__global__ __launch_bounds__(256) void k_attn_out(const int* __restrict__ edge_index) {
    int node = blockIdx.x;
    int tid  = threadIdx.x;
    int b    = node >> 10;

    __shared__ int   nbroff_sh[KNB];
    __shared__ float a_sh[HH][KNB];
    __shared__ float opt_sh[HH * PVn * 3];

    if (tid < KNB) {
        int idx = edge_index[(size_t)node * KNB + tid];
        nbroff_sh[tid] = (b * NN + idx) * PROJ;
    }
    {
        const float* ga = g_attn + (size_t)node * HH * KNB;
        for (int i = tid; i < HH * KNB; i += 256)
            a_sh[i >> 5][i & 31] = ga[i];
    }
    __syncthreads();

    size_t cvb = (size_t)node * CVC;
    for (int oi = tid; oi < CVC; oi += 256) {
        float acc = 0.f;
        bool have = false;
        if (oi < 192) {
            int h = oi >> 4;
            int off = 384 + oi;
            #pragma unroll 8
            for (int k = 0; k < KNB; k++)
                acc += a_sh[h][k] * g_proj[nbroff_sh[k] + off];
            have = true;
        } else if (oi < 480) {
            int j = oi - 192;
            int h = j / 24, r = j % 24;
            int off = 720 + h * 36 + 12 + r;
            #pragma unroll 8
            for (int k = 0; k < KNB; k++)
                acc += a_sh[h][k] * g_proj[nbroff_sh[k] + off];
            opt_sh[j] = acc;
            have = true;
        } else if (oi >= 576) {
            int j = oi - 576;
            int h = j >> 5, c = j & 31;
            const float* eb = g_eo + (size_t)(node * KNB) * EOC + 12 + c;
            #pragma unroll 8
            for (int k = 0; k < KNB; k++)
                acc += a_sh[h][k] * eb[(size_t)k * EOC];
            have = true;
        }
        if (have) {
            __nv_bfloat16 h16, l16;
            cvt_hilo(acc, h16, l16);
            g_cvec_h[cvb + oi] = h16;
            g_cvec_l[cvb + oi] = l16;
        }
    }
    __syncthreads();
    if (tid < HH * PVn) {
        float x = opt_sh[tid*3], y = opt_sh[tid*3+1], zz = opt_sh[tid*3+2];
        float d = sqrtf(x*x + y*y + zz*zz + 1e-8f);
        __nv_bfloat16 h16, l16;
        cvt_hilo(d, h16, l16);
        g_cvec_h[cvb + 480 + tid] = h16;
        g_cvec_l[cvb + 480 + tid] = l16;
    }
}

// ---------------- launch ----------------
extern "C" void kernel_launch(void* const* d_in, const int* in_sizes, int n_in,
                              void* d_out, int out_size) {
    const float* s           = (const float*)d_in[0];
    const float* z           = (const float*)d_in[1];
    const int*   edge_index  = (const int*)  d_in[2];
    // d_in[3] rot, d_in[4] trans: cancel algebraically -> unused
    const float* s_mask      = (const float*)d_in[5];
    const float* ln_s_scale  = (const float*)d_in[6];
    const float* ln_s_bias   = (const float*)d_in[7];
    const float* ln_z_scale  = (const float*)d_in[8];
    const float* ln_z_bias   = (const float*)d_in[9];
    const float* w_q         = (const float*)d_in[10];
    const float* w_k         = (const float*)d_in[11];
    const float* w_v         = (const float*)d_in[12];
    const float* w_q_pts     = (const float*)d_in[13];
    const float* w_kv_pts    = (const float*)d_in[14];
    const float* w_b         = (const float*)d_in[15];
    const float* w_down_z    = (const float*)d_in[16];
    const float* head_weights= (const float*)d_in[17];
    const float* w_out       = (const float*)d_in[18];
    float* out = (float*)d_out;

    const int zsmem = (128 * ZST + 128 * EOCP + 256) * sizeof(float);
    cudaFuncSetAttribute(k_zgemm, cudaFuncAttributeMaxDynamicSharedMemorySize, zsmem);

    void *p_wcat_h, *p_wcat_l, *p_sln_h, *p_sln_l;
    void *p_wout_h, *p_wout_l, *p_cvec_h, *p_cvec_l, *p_proj;
    cudaGetSymbolAddress(&p_wcat_h, g_wcat_h);
    cudaGetSymbolAddress(&p_wcat_l, g_wcat_l);
    cudaGetSymbolAddress(&p_sln_h,  g_sln_h);
    cudaGetSymbolAddress(&p_sln_l,  g_sln_l);
    cudaGetSymbolAddress(&p_wout_h, g_wout_h);
    cudaGetSymbolAddress(&p_wout_l, g_wout_l);
    cudaGetSymbolAddress(&p_cvec_h, g_cvec_h);
    cudaGetSymbolAddress(&p_cvec_l, g_cvec_l);
    cudaGetSymbolAddress(&p_proj,   g_proj);

    pack_all<<<(NW1 + NW2 + NW3 + 255) / 256, 256>>>(
        w_q, w_k, w_v, w_q_pts, w_kv_pts, w_out, w_b, w_down_z);
    k_ln_s<<<NODES, 128>>>(s, ln_s_scale, ln_s_bias);

    // GEMM1: LN(s) @ wcat -> proj   (4096x384)@(384x1152), pure bf16
    tgemm<128><<<dim3(NODES/128, PROJ/128), 256>>>(
        (const __nv_bfloat16*)p_sln_h, (const __nv_bfloat16*)p_sln_l,
        (const __nv_bfloat16*)p_wcat_h, (const __nv_bfloat16*)p_wcat_l,
        (float*)p_proj, CS, PROJ, CS/32);

    // z path (stats + LN + GEMM in one kernel, single z read)
    k_zgemm<<<EDGES / 128, 256, zsmem>>>(z, ln_z_scale, ln_z_bias);

    // attention: logits (smem-heavy, short) then output (occupancy-heavy)
    k_attn_logits<<<NODES, 256, KNB * KST * sizeof(float)>>>(
        edge_index, s_mask, head_weights);
    k_attn_out<<<NODES, 256>>>(edge_index);

    // GEMM2: cvec @ w_out -> out    (4096x960)@(960x384), pure bf16, 64-tiles
    tgemm<64><<<dim3(NODES/64, COUT/128), 256>>>(
        (const __nv_bfloat16*)p_cvec_h, (const __nv_bfloat16*)p_cvec_l,
        (const __nv_bfloat16*)p_wout_h, (const __nv_bfloat16*)p_wout_l,
        out, CVC, COUT, CVC/32);
}

// round 16
// speedup vs baseline: 1.1970x; 1.0805x over previous
#include <cuda_runtime.h>
#include <cuda_bf16.h>
#include <math.h>
#include <stdint.h>

// ---------------- problem constants ----------------
#define BB   4
#define NN   1024
#define KNB  32
#define CS   384
#define CZ   128
#define CH   16
#define HH   12
#define PQn  4
#define PVn  8
#define NODES (BB*NN)        // 4096
#define PROJ  1152           // q(192)+k(192)+v(192)+qpts(144)+kvpts(432)
#define EDGES (NODES*KNB)    // 131072
#define EOC   44             // b_bias(12) + pair(32)
#define WZN   64             // W_z cols padded to 64 (zeros beyond 44)
#define CVC   960            // o(192)+o_pt(288)+dists(96)+o_pair(384)
#define COUT  384

// ---------------- scratch (device globals; no allocation) ----------------
__device__ __nv_bfloat16 g_wcat_h[CS*PROJ];
__device__ __nv_bfloat16 g_wcat_l[CS*PROJ];
__device__ __nv_bfloat16 g_sln_h [NODES*CS];
__device__ __nv_bfloat16 g_sln_l [NODES*CS];
__device__ __nv_bfloat16 g_wout_h[CVC*COUT];
__device__ __nv_bfloat16 g_wout_l[CVC*COUT];
__device__ __nv_bfloat16 g_cvec_h[NODES*CVC];
__device__ __nv_bfloat16 g_cvec_l[NODES*CVC];
__device__ __nv_bfloat16 g_wzh[CZ*WZN];
__device__ __nv_bfloat16 g_wzl[CZ*WZN];
__device__ float g_proj[NODES*PROJ];
__device__ float g_eo  [EDGES*EOC];
__device__ float g_attn[NODES*HH*KNB];

// ---------------- helpers ----------------
__device__ __forceinline__ uint32_t smem_u32(const void* p) {
    uint32_t a;
    asm("{ .reg .u64 t; cvta.to.shared.u64 t, %1; cvt.u32.u64 %0, t; }"
        : "=r"(a) : "l"(p));
    return a;
}
__device__ __forceinline__ void cvt_hilo(float x, __nv_bfloat16& h, __nv_bfloat16& l) {
    h = __float2bfloat16(x);
    l = __float2bfloat16(x - __bfloat162float(h));
}
__device__ __forceinline__ void ldsm4(uint32_t& r0, uint32_t& r1, uint32_t& r2,
                                      uint32_t& r3, uint32_t addr) {
    asm volatile("ldmatrix.sync.aligned.m8n8.x4.shared.b16 {%0,%1,%2,%3}, [%4];"
                 : "=r"(r0), "=r"(r1), "=r"(r2), "=r"(r3) : "r"(addr));
}
__device__ __forceinline__ void ldsm4t(uint32_t& r0, uint32_t& r1, uint32_t& r2,
                                       uint32_t& r3, uint32_t addr) {
    asm volatile("ldmatrix.sync.aligned.m8n8.x4.trans.shared.b16 {%0,%1,%2,%3}, [%4];"
                 : "=r"(r0), "=r"(r1), "=r"(r2), "=r"(r3) : "r"(addr));
}
__device__ __forceinline__ void mma16816(float* c, const uint32_t* a, const uint32_t* b) {
    asm volatile(
        "mma.sync.aligned.m16n8k16.row.col.f32.bf16.bf16.f32 "
        "{%0,%1,%2,%3}, {%4,%5,%6,%7}, {%8,%9}, {%0,%1,%2,%3};"
        : "+f"(c[0]), "+f"(c[1]), "+f"(c[2]), "+f"(c[3])
        : "r"(a[0]), "r"(a[1]), "r"(a[2]), "r"(a[3]), "r"(b[0]), "r"(b[1]));
}

// ================= merged weight packing (fp32 -> bf16 hi/lo) ==============
#define NW1 (CS*PROJ)
#define NW2 (CVC*COUT)
#define NW3 (CZ*WZN)
__global__ void pack_all(const float* __restrict__ wq, const float* __restrict__ wk,
                         const float* __restrict__ wv, const float* __restrict__ wqp,
                         const float* __restrict__ wkv, const float* __restrict__ wo,
                         const float* __restrict__ wb, const float* __restrict__ wdz) {
    int idx = blockIdx.x * 256 + threadIdx.x;
    if (idx < NW1) {
        int i = idx / PROJ, j = idx % PROJ;
        float v;
        if      (j < 192) v = wq [i*192 + j];
        else if (j < 384) v = wk [i*192 + j - 192];
        else if (j < 576) v = wv [i*192 + j - 384];
        else if (j < 720) v = wqp[i*144 + j - 576];
        else              v = wkv[i*432 + j - 720];
        __nv_bfloat16 h, l;
        cvt_hilo(v, h, l);
        g_wcat_h[idx] = h;
        g_wcat_l[idx] = l;
    } else if (idx < NW1 + NW2) {
        int j = idx - NW1;
        __nv_bfloat16 h, l;
        cvt_hilo(wo[j], h, l);
        g_wout_h[j] = h;
        g_wout_l[j] = l;
    } else if (idx < NW1 + NW2 + NW3) {
        int t = idx - NW1 - NW2;
        int row = t >> 6, col = t & 63;
        float v = (col < 12) ? wb[row*12 + col]
                : (col < EOC) ? wdz[row*32 + col - 12] : 0.f;
        __nv_bfloat16 h, l;
        cvt_hilo(v, h, l);
        g_wzh[t] = h;
        g_wzl[t] = l;
    }
}

// ---------------- s layernorm -> bf16 hi/lo (one block per node) ----------
__global__ __launch_bounds__(128) void k_ln_s(const float* __restrict__ s,
                                              const float* __restrict__ gam,
                                              const float* __restrict__ bet) {
    int node = blockIdx.x;
    int tid  = threadIdx.x;
    const float* x = s + (size_t)node * CS;
    float v0 = x[tid], v1 = x[tid + 128], v2 = x[tid + 256];
    float sum = v0 + v1 + v2;
    float ssq = v0*v0 + v1*v1 + v2*v2;
    #pragma unroll
    for (int o = 16; o; o >>= 1) {
        sum += __shfl_xor_sync(0xffffffffu, sum, o);
        ssq += __shfl_xor_sync(0xffffffffu, ssq, o);
    }
    __shared__ float sa[4], sb[4];
    int w = tid >> 5, l = tid & 31;
    if (l == 0) { sa[w] = sum; sb[w] = ssq; }
    __syncthreads();
    sum = sa[0] + sa[1] + sa[2] + sa[3];
    ssq = sb[0] + sb[1] + sb[2] + sb[3];
    float mean = sum * (1.0f / CS);
    float var  = ssq * (1.0f / CS) - mean * mean;
    float rstd = rsqrtf(var + 1e-5f);
    size_t base = (size_t)node * CS;
    #pragma unroll
    for (int i = 0; i < 3; i++) {
        float v = (i == 0) ? v0 : (i == 1) ? v1 : v2;
        int c = tid + i * 128;
        float y = (v - mean) * rstd * gam[c] + bet[c];
        __nv_bfloat16 h, lo;
        cvt_hilo(y, h, lo);
        g_sln_h[base + c] = h;
        g_sln_l[base + c] = lo;
    }
}

// ================= pure-bf16 tensor-core GEMM (3-term hi/lo) ===============
#define AST 40
#define BST 136

template<int BM>
__global__ __launch_bounds__(256, 2) void tgemm(const __nv_bfloat16* __restrict__ A_h,
                                                const __nv_bfloat16* __restrict__ A_l,
                                                const __nv_bfloat16* __restrict__ B_h,
                                                const __nv_bfloat16* __restrict__ B_l,
                                                float* __restrict__ C,
                                                int Kd, int Nd, int nk) {
    constexpr int MT = BM / 32;
    constexpr int AL = BM / 64;
    __shared__ __nv_bfloat16 Ah[BM * AST];
    __shared__ __nv_bfloat16 Al[BM * AST];
    __shared__ __nv_bfloat16 Bh[32 * BST];
    __shared__ __nv_bfloat16 Bl[32 * BST];

    int tid = threadIdx.x, wid = tid >> 5, lane = tid & 31;
    int m0 = blockIdx.x * BM, n0 = blockIdx.y * 128;
    int wm = (wid >> 2) * (BM / 2);
    int wn = (wid & 3) * 32;

    float acc[MT][4][4];
    #pragma unroll
    for (int i = 0; i < MT; i++)
        #pragma unroll
        for (int j = 0; j < 4; j++)
            #pragma unroll
            for (int r = 0; r < 4; r++) acc[i][j][r] = 0.f;

    uint32_t ah_base = smem_u32(Ah), al_base = smem_u32(Al);
    uint32_t bh_base = smem_u32(Bh), bl_base = smem_u32(Bl);

    int a_row = wm + (lane & 15);
    int a_col = (lane >> 4) << 3;
    int b_row = (lane & 7) + ((lane >> 3) & 1) * 8;
    int b_col = wn + ((lane >> 4) << 3);

    uint4 arh[AL], arl[AL], brh[2], brl[2];

    auto loadA = [&](int c) {
        int k0 = c * 32;
        #pragma unroll
        for (int t = 0; t < AL; t++) {
            int f = tid + t * 256;
            int row = f >> 2, col = (f & 3) * 8;
            size_t off = (size_t)(m0 + row) * Kd + k0 + col;
            arh[t] = *(const uint4*)(A_h + off);
            arl[t] = *(const uint4*)(A_l + off);
        }
    };
    auto loadB = [&](int c) {
        int k0 = c * 32;
        #pragma unroll
        for (int t = 0; t < 2; t++) {
            int f = tid + t * 256;
            int kr = f >> 4, nn = (f & 15) * 8;
            size_t off = (size_t)(k0 + kr) * Nd + n0 + nn;
            brh[t] = *(const uint4*)(B_h + off);
            brl[t] = *(const uint4*)(B_l + off);
        }
    };
    auto storeAB = [&]() {
        #pragma unroll
        for (int t = 0; t < AL; t++) {
            int f = tid + t * 256;
            int row = f >> 2, col = (f & 3) * 8;
            *(uint4*)&Ah[row*AST + col] = arh[t];
            *(uint4*)&Al[row*AST + col] = arl[t];
        }
        #pragma unroll
        for (int t = 0; t < 2; t++) {
            int f = tid + t * 256;
            int kr = f >> 4, nn = (f & 15) * 8;
            *(uint4*)&Bh[kr*BST + nn] = brh[t];
            *(uint4*)&Bl[kr*BST + nn] = brl[t];
        }
    };

    loadA(0); loadB(0);

    for (int c = 0; c < nk; c++) {
        storeAB();
        __syncthreads();
        if (c + 1 < nk) { loadA(c + 1); loadB(c + 1); }

        #pragma unroll
        for (int pass = 0; pass < 3; pass++) {
            uint32_t abase = (pass == 1) ? al_base : ah_base;
            uint32_t bbase = (pass == 2) ? bl_base : bh_base;
            #pragma unroll
            for (int ks = 0; ks < 32; ks += 16) {
                uint32_t af[MT][4];
                #pragma unroll
                for (int mt = 0; mt < MT; mt++) {
                    uint32_t addr = abase +
                        (uint32_t)(((a_row + mt*16) * AST + ks + a_col) * 2);
                    ldsm4(af[mt][0], af[mt][1], af[mt][2], af[mt][3], addr);
                }
                uint32_t bfr[4][2];
                #pragma unroll
                for (int nt16 = 0; nt16 < 2; nt16++) {
                    uint32_t addr = bbase +
                        (uint32_t)(((ks + b_row) * BST + b_col + nt16*16) * 2);
                    ldsm4t(bfr[nt16*2][0], bfr[nt16*2][1],
                           bfr[nt16*2+1][0], bfr[nt16*2+1][1], addr);
                }
                #pragma unroll
                for (int mt = 0; mt < MT; mt++)
                    #pragma unroll
                    for (int nt = 0; nt < 4; nt++)
                        mma16816(acc[mt][nt], af[mt], bfr[nt]);
            }
        }
        __syncthreads();
    }

    int er = lane >> 2;
    int ec = (lane & 3) * 2;
    #pragma unroll
    for (int mt = 0; mt < MT; mt++) {
        #pragma unroll
        for (int nt = 0; nt < 4; nt++) {
            int row = m0 + wm + mt*16 + er;
            int col = n0 + wn + nt*8 + ec;
            *(float2*)(C + (size_t)row * Nd + col) =
                make_float2(acc[mt][nt][0], acc[mt][nt][1]);
            *(float2*)(C + (size_t)(row + 8) * Nd + col) =
                make_float2(acc[mt][nt][2], acc[mt][nt][3]);
        }
    }
}

// ======= z GEMM: stats + LN fused, tensor-core bf16x3, W padded to 64 ======
#define BSTZ 72   // W smem row stride in bf16 (16B multiple)

extern __shared__ float dynsm[];
__global__ __launch_bounds__(256, 2) void k_zgemm_t(const float* __restrict__ z,
                                                    const float* __restrict__ zsc,
                                                    const float* __restrict__ zbi) {
    float* mean_sh = dynsm;                 // [128]
    float* rstd_sh = mean_sh + 128;         // [128]
    __nv_bfloat16* Ah = (__nv_bfloat16*)(rstd_sh + 128);   // [128][AST]
    __nv_bfloat16* Al = Ah + 128 * AST;
    __nv_bfloat16* Wh = Al + 128 * AST;                    // [128][BSTZ]
    __nv_bfloat16* Wl = Wh + 128 * BSTZ;

    int tid = threadIdx.x, wid = tid >> 5, lane = tid & 31;
    int r0 = blockIdx.x * 128;

    // ---- load W (bf16 hi/lo, [128][64] -> smem stride BSTZ)
    #pragma unroll
    for (int t = 0; t < 4; t++) {
        int f = tid + t * 256;
        int row = f >> 3, col = (f & 7) * 8;
        *(uint4*)&Wh[row*BSTZ + col] = *(const uint4*)(g_wzh + row*64 + col);
        *(uint4*)&Wl[row*BSTZ + col] = *(const uint4*)(g_wzl + row*64 + col);
    }

    // ---- per-row stats from gmem (warp w -> rows w*16..w*16+15)
    for (int rr = 0; rr < 16; rr++) {
        int row = wid * 16 + rr;
        float4 v = *(const float4*)(z + (size_t)(r0 + row) * CZ + lane * 4);
        float s1 = v.x + v.y + v.z + v.w;
        float s2 = v.x*v.x + v.y*v.y + v.z*v.z + v.w*v.w;
        #pragma unroll
        for (int o = 16; o; o >>= 1) {
            s1 += __shfl_xor_sync(0xffffffffu, s1, o);
            s2 += __shfl_xor_sync(0xffffffffu, s2, o);
        }
        if (lane == 0) {
            float mean = s1 * (1.0f / CZ);
            float var  = s2 * (1.0f / CZ) - mean * mean;
            mean_sh[row] = mean;
            rstd_sh[row] = rsqrtf(var + 1e-5f);
        }
    }
    __syncthreads();

    // ---- warp tiling: 4M x 2N, warp tile 32x32
    int wm = (wid >> 1) * 32;
    int wn = (wid & 1) * 32;
    int a_row = wm + (lane & 15);
    int a_col = (lane >> 4) << 3;
    int b_row = (lane & 7) + ((lane >> 3) & 1) * 8;
    int b_col = wn + ((lane >> 4) << 3);
    uint32_t ah_base = smem_u32(Ah), al_base = smem_u32(Al);
    uint32_t wh_base = smem_u32(Wh), wl_base = smem_u32(Wl);

    float acc[2][4][4];
    #pragma unroll
    for (int i = 0; i < 2; i++)
        #pragma unroll
        for (int j = 0; j < 4; j++)
            #pragma unroll
            for (int r = 0; r < 4; r++) acc[i][j][r] = 0.f;

    for (int c = 0; c < 4; c++) {
        int k0 = c * 32;
        // convert LN(z) chunk -> Ah/Al (z re-read from L2)
        #pragma unroll
        for (int t = 0; t < 4; t++) {
            int f = tid + t * 256;
            int row = f >> 3, col = (f & 7) * 4;
            float4 v = *(const float4*)(z + (size_t)(r0 + row) * CZ + k0 + col);
            float mean = mean_sh[row], rstd = rstd_sh[row];
            v.x = (v.x - mean) * rstd * __ldg(zsc + k0 + col + 0) + __ldg(zbi + k0 + col + 0);
            v.y = (v.y - mean) * rstd * __ldg(zsc + k0 + col + 1) + __ldg(zbi + k0 + col + 1);
            v.z = (v.z - mean) * rstd * __ldg(zsc + k0 + col + 2) + __ldg(zbi + k0 + col + 2);
            v.w = (v.w - mean) * rstd * __ldg(zsc + k0 + col + 3) + __ldg(zbi + k0 + col + 3);
            __nv_bfloat16 h0,h1,h2,h3,l0,l1,l2,l3;
            cvt_hilo(v.x,h0,l0); cvt_hilo(v.y,h1,l1);
            cvt_hilo(v.z,h2,l2); cvt_hilo(v.w,h3,l3);
            *(__nv_bfloat162*)&Ah[row*AST + col    ] = __nv_bfloat162(h0,h1);
            *(__nv_bfloat162*)&Ah[row*AST + col + 2] = __nv_bfloat162(h2,h3);
            *(__nv_bfloat162*)&Al[row*AST + col    ] = __nv_bfloat162(l0,l1);
            *(__nv_bfloat162*)&Al[row*AST + col + 2] = __nv_bfloat162(l2,l3);
        }
        __syncthreads();

        #pragma unroll
        for (int pass = 0; pass < 3; pass++) {
            uint32_t abase = (pass == 1) ? al_base : ah_base;
            uint32_t bbase = (pass == 2) ? wl_base : wh_base;
            #pragma unroll
            for (int ks = 0; ks < 32; ks += 16) {
                uint32_t af[2][4];
                #pragma unroll
                for (int mt = 0; mt < 2; mt++) {
                    uint32_t addr = abase +
                        (uint32_t)(((a_row + mt*16) * AST + ks + a_col) * 2);
                    ldsm4(af[mt][0], af[mt][1], af[mt][2], af[mt][3], addr);
                }
                uint32_t bfr[4][2];
                #pragma unroll
                for (int nt16 = 0; nt16 < 2; nt16++) {
                    uint32_t addr = bbase +
                        (uint32_t)(((k0 + ks + b_row) * BSTZ + b_col + nt16*16) * 2);
                    ldsm4t(bfr[nt16*2][0], bfr[nt16*2][1],
                           bfr[nt16*2+1][0], bfr[nt16*2+1][1], addr);
                }
                #pragma unroll
                for (int mt = 0; mt < 2; mt++)
                    #pragma unroll
                    for (int nt = 0; nt < 4; nt++)
                        mma16816(acc[mt][nt], af[mt], bfr[nt]);
            }
        }
        __syncthreads();
    }

    // ---- epilogue to g_eo (cols < 44)
    int er = lane >> 2;
    int ec = (lane & 3) * 2;
    #pragma unroll
    for (int mt = 0; mt < 2; mt++) {
        #pragma unroll
        for (int nt = 0; nt < 4; nt++) {
            int col = wn + nt*8 + ec;
            if (col < EOC) {
                int row = r0 + wm + mt*16 + er;
                *(float2*)(g_eo + (size_t)row * EOC + col) =
                    make_float2(acc[mt][nt][0], acc[mt][nt][1]);
                *(float2*)(g_eo + (size_t)(row + 8) * EOC + col) =
                    make_float2(acc[mt][nt][2], acc[mt][nt][3]);
            }
        }
    }
}

// ---------------- attention logits: one block (256 thr) per node -----------
#define KST 337   // smem row stride (floats): 192 k + 144 kpts

__global__ __launch_bounds__(256) void k_attn_logits(const int*   __restrict__ edge_index,
                                                     const float* __restrict__ s_mask,
                                                     const float* __restrict__ head_w) {
    float* kv_sh = dynsm;              // [KNB][KST]
    int node = blockIdx.x;
    int tid  = threadIdx.x;
    int b    = node >> 10;

    __shared__ int   nbroff_sh[KNB];
    __shared__ float msk_sh[KNB];
    __shared__ float q_sh[HH * CH];
    __shared__ float qp_sh[HH * PQn * 3];
    __shared__ float hw_sh[HH];
    __shared__ float b_sh[HH][KNB];

    if (tid < KNB) {
        int idx = edge_index[(size_t)node * KNB + tid];
        nbroff_sh[tid] = (b * NN + idx) * PROJ;
        msk_sh[tid]    = s_mask[node] * s_mask[b * NN + idx];
    }
    if (tid < HH)
        hw_sh[tid] = log1pf(__expf(head_w[tid])) * 0.13608276348795434f;
    __syncthreads();

    for (int idx = tid; idx < KNB * 192; idx += 256) {
        int k = idx / 192, c = idx - k * 192;
        kv_sh[k * KST + c] = g_proj[nbroff_sh[k] + 192 + c];
    }
    for (int idx = tid; idx < KNB * 144; idx += 256) {
        int k = idx / 144, j = idx - k * 144;
        int h = j / 12, r = j - h * 12;
        kv_sh[k * KST + 192 + j] = g_proj[nbroff_sh[k] + 720 + h * 36 + r];
    }
    for (int idx = tid; idx < KNB * HH; idx += 256) {
        int k = idx / HH, h = idx - k * HH;
        b_sh[h][k] = g_eo[(size_t)(node * KNB + k) * EOC + h];
    }
    for (int i = tid; i < HH * CH; i += 256)
        q_sh[i] = g_proj[(size_t)node * PROJ + i];
    for (int i = tid; i < HH * PQn * 3; i += 256)
        qp_sh[i] = g_proj[(size_t)node * PROJ + 576 + i];
    __syncthreads();

    int lane = tid & 31, warp = tid >> 5;
    float mk = msk_sh[lane];
    const float* kr = kv_sh + lane * KST;
    float* ga = g_attn + (size_t)node * HH * KNB;

    #pragma unroll
    for (int rep = 0; rep < 2; rep++) {
        if (rep == 1 && warp >= 4) break;
        int h = (rep == 0) ? warp : 8 + warp;
        float dot = 0.f;
        #pragma unroll
        for (int c = 0; c < 16; c++)
            dot += q_sh[h * CH + c] * kr[h * CH + c];
        float sq = 0.f;
        #pragma unroll
        for (int j = 0; j < 12; j++) {
            float d = qp_sh[h * 12 + j] - kr[192 + h * 12 + j];
            sq += d * d;
        }
        float logit = dot * 0.14433756729740643f
                    + b_sh[h][lane] * 0.5773502691896258f
                    - 0.5f * hw_sh[h] * sq
                    + 100000.0f * (mk - 1.0f);
        float mx = logit;
        #pragma unroll
        for (int o = 16; o; o >>= 1) mx = fmaxf(mx, __shfl_xor_sync(0xffffffffu, mx, o));
        float e = __expf(logit - mx);
        float sm = e;
        #pragma unroll
        for (int o = 16; o; o >>= 1) sm += __shfl_xor_sync(0xffffffffu, sm, o);
        ga[h * KNB + lane] = e / sm;
    }
}

// ---------------- attention output: one block (256 thr) per node ----------
__global__ __launch_bounds__(256) void k_attn_out(const int* __restrict__ edge_index) {
    int node = blockIdx.x;
    int tid  = threadIdx.x;
    int b    = node >> 10;

    __shared__ int   nbroff_sh[KNB];
    __shared__ float a_sh[HH][KNB];
    __shared__ float opt_sh[HH * PVn * 3];

    if (tid < KNB) {
        int idx = edge_index[(size_t)node * KNB + tid];
        nbroff_sh[tid] = (b * NN + idx) * PROJ;
    }
    {
        const float* ga = g_attn + (size_t)node * HH * KNB;
        for (int i = tid; i < HH * KNB; i += 256)
            a_sh[i >> 5][i & 31] = ga[i];
    }
    __syncthreads();

    size_t cvb = (size_t)node * CVC;
    for (int oi = tid; oi < CVC; oi += 256) {
        float acc = 0.f;
        bool have = false;
        if (oi < 192) {
            int h = oi >> 4;
            int off = 384 + oi;
            #pragma unroll 8
            for (int k = 0; k < KNB; k++)
                acc += a_sh[h][k] * g_proj[nbroff_sh[k] + off];
            have = true;
        } else if (oi < 480) {
            int j = oi - 192;
            int h = j / 24, r = j % 24;
            int off = 720 + h * 36 + 12 + r;
            #pragma unroll 8
            for (int k = 0; k < KNB; k++)
                acc += a_sh[h][k] * g_proj[nbroff_sh[k] + off];
            opt_sh[j] = acc;
            have = true;
        } else if (oi >= 576) {
            int j = oi - 576;
            int h = j >> 5, c = j & 31;
            const float* eb = g_eo + (size_t)(node * KNB) * EOC + 12 + c;
            #pragma unroll 8
            for (int k = 0; k < KNB; k++)
                acc += a_sh[h][k] * eb[(size_t)k * EOC];
            have = true;
        }
        if (have) {
            __nv_bfloat16 h16, l16;
            cvt_hilo(acc, h16, l16);
            g_cvec_h[cvb + oi] = h16;
            g_cvec_l[cvb + oi] = l16;
        }
    }
    __syncthreads();
    if (tid < HH * PVn) {
        float x = opt_sh[tid*3], y = opt_sh[tid*3+1], zz = opt_sh[tid*3+2];
        float d = sqrtf(x*x + y*y + zz*zz + 1e-8f);
        __nv_bfloat16 h16, l16;
        cvt_hilo(d, h16, l16);
        g_cvec_h[cvb + 480 + tid] = h16;
        g_cvec_l[cvb + 480 + tid] = l16;
    }
}

// ---------------- launch ----------------
extern "C" void kernel_launch(void* const* d_in, const int* in_sizes, int n_in,
                              void* d_out, int out_size) {
    const float* s           = (const float*)d_in[0];
    const float* z           = (const float*)d_in[1];
    const int*   edge_index  = (const int*)  d_in[2];
    // d_in[3] rot, d_in[4] trans: cancel algebraically -> unused
    const float* s_mask      = (const float*)d_in[5];
    const float* ln_s_scale  = (const float*)d_in[6];
    const float* ln_s_bias   = (const float*)d_in[7];
    const float* ln_z_scale  = (const float*)d_in[8];
    const float* ln_z_bias   = (const float*)d_in[9];
    const float* w_q         = (const float*)d_in[10];
    const float* w_k         = (const float*)d_in[11];
    const float* w_v         = (const float*)d_in[12];
    const float* w_q_pts     = (const float*)d_in[13];
    const float* w_kv_pts    = (const float*)d_in[14];
    const float* w_b         = (const float*)d_in[15];
    const float* w_down_z    = (const float*)d_in[16];
    const float* head_weights= (const float*)d_in[17];
    const float* w_out       = (const float*)d_in[18];
    float* out = (float*)d_out;

    // zgemm smem: stats 256 f + Ah/Al 2*128*AST bf16 + Wh/Wl 2*128*BSTZ bf16
    const int zsmem = 256 * 4 + (2 * 128 * AST + 2 * 128 * BSTZ) * 2;
    cudaFuncSetAttribute(k_zgemm_t, cudaFuncAttributeMaxDynamicSharedMemorySize, zsmem);

    void *p_wcat_h, *p_wcat_l, *p_sln_h, *p_sln_l;
    void *p_wout_h, *p_wout_l, *p_cvec_h, *p_cvec_l, *p_proj;
    cudaGetSymbolAddress(&p_wcat_h, g_wcat_h);
    cudaGetSymbolAddress(&p_wcat_l, g_wcat_l);
    cudaGetSymbolAddress(&p_sln_h,  g_sln_h);
    cudaGetSymbolAddress(&p_sln_l,  g_sln_l);
    cudaGetSymbolAddress(&p_wout_h, g_wout_h);
    cudaGetSymbolAddress(&p_wout_l, g_wout_l);
    cudaGetSymbolAddress(&p_cvec_h, g_cvec_h);
    cudaGetSymbolAddress(&p_cvec_l, g_cvec_l);
    cudaGetSymbolAddress(&p_proj,   g_proj);

    pack_all<<<(NW1 + NW2 + NW3 + 255) / 256, 256>>>(
        w_q, w_k, w_v, w_q_pts, w_kv_pts, w_out, w_b, w_down_z);
    k_ln_s<<<NODES, 128>>>(s, ln_s_scale, ln_s_bias);

    // GEMM1: LN(s) @ wcat -> proj   (4096x384)@(384x1152), pure bf16
    tgemm<128><<<dim3(NODES/128, PROJ/128), 256>>>(
        (const __nv_bfloat16*)p_sln_h, (const __nv_bfloat16*)p_sln_l,
        (const __nv_bfloat16*)p_wcat_h, (const __nv_bfloat16*)p_wcat_l,
        (float*)p_proj, CS, PROJ, CS/32);

    // z path: stats + LN + tensor-core GEMM fused, single-ish z read
    k_zgemm_t<<<EDGES / 128, 256, zsmem>>>(z, ln_z_scale, ln_z_bias);

    // attention: logits (smem-heavy, short) then output (occupancy-heavy)
    k_attn_logits<<<NODES, 256, KNB * KST * sizeof(float)>>>(
        edge_index, s_mask, head_weights);
    k_attn_out<<<NODES, 256>>>(edge_index);

    // GEMM2: cvec @ w_out -> out    (4096x960)@(960x384), pure bf16, 64-tiles
    tgemm<64><<<dim3(NODES/64, COUT/128), 256>>>(
        (const __nv_bfloat16*)p_cvec_h, (const __nv_bfloat16*)p_cvec_l,
        (const __nv_bfloat16*)p_wout_h, (const __nv_bfloat16*)p_wout_l,
        out, CVC, COUT, CVC/32);
}